// round 17
// baseline (speedup 1.0000x reference)
#include <cuda_runtime.h>
#include <cstdint>

#define N_NODES 50000
#define N_EDGES 800000
#define NUM_GRAPHS 256
#define IN_DIM 128
#define H_DIM 64
#define HID 256
#define EPS 1e-5f

#define SCAN_B 1024
#define SCAN_NB ((N_NODES + SCAN_B - 1) / SCAN_B)   // 49

// ---------------- scratch (static device memory; no allocation) ----------------
__device__ int   g_src[N_EDGES];
__device__ int   g_dst[N_EDGES];
__device__ int   g_batch[N_NODES];
__device__ int   g_deg[N_NODES];
__device__ int   g_off[N_NODES];
__device__ int   g_cur[N_NODES];
__device__ int   g_csr[N_EDGES];
__device__ int   g_bsum[SCAN_NB];
__device__ float g_yl[N_NODES * H_DIM];
__device__ float g_yr[N_NODES * H_DIM];
__device__ float g_hA[N_NODES * H_DIM];
__device__ float g_hB[N_NODES * H_DIM];
__device__ float g_pool[NUM_GRAPHS * H_DIM];
__device__ float g_pcnt[NUM_GRAPHS];
__device__ float g_m1[NUM_GRAPHS * HID];
__device__ float g_m2[NUM_GRAPHS * (HID / 2)];
__device__ float g_m3[NUM_GRAPHS * (HID / 4)];

__device__ __forceinline__ float* buf_by_id(int id) {
    switch (id) {
        case 0: return g_yl;
        case 1: return g_yr;
        case 2: return g_hA;
        case 3: return g_hB;
        default: return g_pool;
    }
}

// Per-block int64 detection from the EDGE buffer: read first 256 int64 slots.
__device__ __forceinline__ int detect_is64(const long long* __restrict__ e,
                                           int* s_flag) {
    int t = threadIdx.x;
    if (t == 0) *s_flag = 1;
    __syncthreads();
    if (t < 256) {
        long long v = e[t];
        if (v < 0 || v >= (long long)N_NODES) *s_flag = 0;
    }
    __syncthreads();
    return *s_flag;
}

// ---------------- zero scratch (must precede convert_edges histogram) ----------
__global__ void zero_kernel() {
    int i = blockIdx.x * blockDim.x + threadIdx.x;
    if (i < N_NODES) g_deg[i] = 0;
    if (i < NUM_GRAPHS * H_DIM) g_pool[i] = 0.0f;
    if (i < NUM_GRAPHS) g_pcnt[i] = 0.0f;
}

// convert + degree histogram fused; local dtype detection
__global__ void convert_edges(const void* __restrict__ e) {
    __shared__ int s_flag;
    int is64 = detect_is64((const long long*)e, &s_flag);
    int i = blockIdx.x * blockDim.x + threadIdx.x;
    if (i >= N_EDGES) return;
    int s, d;
    if (is64) {
        const long long* p = (const long long*)e;
        s = (int)p[i];
        d = (int)p[N_EDGES + i];
    } else {
        const int* p = (const int*)e;
        s = p[i];
        d = p[N_EDGES + i];
    }
    g_src[i] = s;
    g_dst[i] = d;
    atomicAdd(&g_deg[d], 1);
}

__global__ void convert_batch(const void* __restrict__ bptr,
                              const void* __restrict__ e) {
    __shared__ int s_flag;
    int is64 = detect_is64((const long long*)e, &s_flag);
    int i = blockIdx.x * blockDim.x + threadIdx.x;
    if (i >= N_NODES) return;
    if (is64) g_batch[i] = (int)((const long long*)bptr)[i];
    else      g_batch[i] = ((const int*)bptr)[i];
}

// ---------------- CSR build: blocksum + fused block_scan ----------------------
__global__ void blocksum_kernel() {
    __shared__ int s[SCAN_B];
    int t = threadIdx.x;
    int i = blockIdx.x * SCAN_B + t;
    s[t] = (i < N_NODES) ? g_deg[i] : 0;
    __syncthreads();
    for (int st = SCAN_B / 2; st > 0; st >>= 1) {
        if (t < st) s[t] += s[t + st];
        __syncthreads();
    }
    if (t == 0) g_bsum[blockIdx.x] = s[0];
}

__global__ void block_scan_kernel() {
    __shared__ int s[SCAN_B];
    __shared__ int sb[64];
    int t = threadIdx.x;
    int i = blockIdx.x * SCAN_B + t;
    if (t < 64) sb[t] = (t < SCAN_NB && t < (int)blockIdx.x) ? g_bsum[t] : 0;
    int v = (i < N_NODES) ? g_deg[i] : 0;
    s[t] = v;
    __syncthreads();
    if (t < 32) sb[t] += sb[t + 32];
    __syncthreads();
    if (t < 16) sb[t] += sb[t + 16];
    __syncthreads();
    if (t < 8) sb[t] += sb[t + 8];
    __syncthreads();
    if (t < 4) sb[t] += sb[t + 4];
    __syncthreads();
    if (t < 2) sb[t] += sb[t + 2];
    __syncthreads();
    if (t < 1) sb[t] += sb[t + 1];
    __syncthreads();
    int boff = sb[0];
    for (int off = 1; off < SCAN_B; off <<= 1) {
        int x = (t >= off) ? s[t - off] : 0;
        __syncthreads();
        s[t] += x;
        __syncthreads();
    }
    if (i < N_NODES) {
        int o = boff + s[t] - v;  // exclusive
        g_off[i] = o;
        g_cur[i] = o;
    }
}

__global__ void fill_kernel() {
    int i = blockIdx.x * blockDim.x + threadIdx.x;
    if (i < N_EDGES) {
        int p = atomicAdd(&g_cur[g_dst[i]], 1);
        g_csr[p] = g_src[i];
    }
}

// ---------------- tensor-core dual GEMM: 3-pass tf32 split (fp32 accuracy) ----
// yl = in @ Wl, yr = in @ Wr + bias.  Nout = 64.  K in {128, 64}.
// 256 threads = 8 warps; warp w owns rows [blk*128 + w*16, +16), all 64 cols.
// W staged per 32-k tile in smem as interleaved (hi, lo) float2 with k-row
// stride 68 pairs (136 words == 8 mod 32 -> conflict-free LDS.64 fragments).
// acc = Ahi*Whi + Ahi*Wlo + Alo*Whi  (error ~3*2^-22, fp32-class).

#define WKP 68   // float2 pairs per k-row in smem (64 + 4 pad)

__device__ __forceinline__ float tf32f(float x) {
    uint32_t r;
    asm("cvt.rna.tf32.f32 %0, %1;" : "=r"(r) : "f"(x));
    return __uint_as_float(r);
}

__device__ __forceinline__ void mma_tf32(float* c,
                                         uint32_t a0, uint32_t a1,
                                         uint32_t a2, uint32_t a3,
                                         uint32_t b0, uint32_t b1) {
    asm volatile(
        "mma.sync.aligned.m16n8k8.row.col.f32.tf32.tf32.f32 "
        "{%0,%1,%2,%3}, {%4,%5,%6,%7}, {%8,%9}, {%0,%1,%2,%3};\n"
        : "+f"(c[0]), "+f"(c[1]), "+f"(c[2]), "+f"(c[3])
        : "r"(a0), "r"(a1), "r"(a2), "r"(a3), "r"(b0), "r"(b1));
}

__global__ __launch_bounds__(256)
void gemm_dual_tc3(const float* __restrict__ xin, int in_id,
                   const float* __restrict__ Wl,
                   const float* __restrict__ bias,
                   const float* __restrict__ Wr, int K) {
    const float* in = (in_id < 0) ? xin : buf_by_id(in_id);
    const int M = N_NODES;

    // [mat][k within tile][n] -> (hi, lo)
    __shared__ float2 sW[2][32][WKP];

    int tid = threadIdx.x;
    int lane = tid & 31;
    int warp = tid >> 5;
    int kq = lane & 3;        // 0..3
    int lg = lane >> 2;       // 0..7
    int r0 = blockIdx.x * 128 + warp * 16 + lg;
    int r1 = r0 + 8;
    bool v0 = r0 < M, v1 = r1 < M;

    float accL[8][4];
    float accR[8][4];
#pragma unroll
    for (int j = 0; j < 8; j++)
#pragma unroll
        for (int c = 0; c < 4; c++) { accL[j][c] = 0.0f; accR[j][c] = 0.0f; }

    const float* rowp0 = in + (size_t)(v0 ? r0 : 0) * K;
    const float* rowp1 = in + (size_t)(v1 ? r1 : 0) * K;

    for (int kt = 0; kt < K; kt += 32) {
        __syncthreads();
        // fill W tile: 2 mats x 32 k x 64 n = 4096 elems, 16 per thread
#pragma unroll
        for (int i = 0; i < 8; i++) {
            int idx = tid + i * 256;       // 0..2047
            int k = idx >> 6;
            int n = idx & 63;
            float wl = Wl[(size_t)(kt + k) * 64 + n];
            float wr = Wr[(size_t)(kt + k) * 64 + n];
            float wlh = tf32f(wl);
            float wrh = tf32f(wr);
            sW[0][k][n] = make_float2(wlh, tf32f(wl - wlh));
            sW[1][k][n] = make_float2(wrh, tf32f(wr - wrh));
        }
        __syncthreads();

#pragma unroll
        for (int k8 = 0; k8 < 4; k8++) {
            int kb = kt + k8 * 8;
            float x0 = v0 ? rowp0[kb + kq] : 0.0f;
            float x1 = v1 ? rowp1[kb + kq] : 0.0f;
            float x2 = v0 ? rowp0[kb + kq + 4] : 0.0f;
            float x3 = v1 ? rowp1[kb + kq + 4] : 0.0f;
            float h0 = tf32f(x0), h1 = tf32f(x1), h2 = tf32f(x2), h3 = tf32f(x3);
            uint32_t ah0 = __float_as_uint(h0);
            uint32_t ah1 = __float_as_uint(h1);
            uint32_t ah2 = __float_as_uint(h2);
            uint32_t ah3 = __float_as_uint(h3);
            uint32_t al0 = __float_as_uint(tf32f(x0 - h0));
            uint32_t al1 = __float_as_uint(tf32f(x1 - h1));
            uint32_t al2 = __float_as_uint(tf32f(x2 - h2));
            uint32_t al3 = __float_as_uint(tf32f(x3 - h3));

            int ka = k8 * 8 + kq;
#pragma unroll
            for (int j = 0; j < 8; j++) {
                int n = lg + 8 * j;
                float2 pl0 = sW[0][ka][n];
                float2 pl1 = sW[0][ka + 4][n];
                uint32_t blh0 = __float_as_uint(pl0.x);
                uint32_t blh1 = __float_as_uint(pl1.x);
                uint32_t bll0 = __float_as_uint(pl0.y);
                uint32_t bll1 = __float_as_uint(pl1.y);
                mma_tf32(accL[j], ah0, ah1, ah2, ah3, blh0, blh1);
                mma_tf32(accL[j], ah0, ah1, ah2, ah3, bll0, bll1);
                mma_tf32(accL[j], al0, al1, al2, al3, blh0, blh1);

                float2 pr0 = sW[1][ka][n];
                float2 pr1 = sW[1][ka + 4][n];
                uint32_t brh0 = __float_as_uint(pr0.x);
                uint32_t brh1 = __float_as_uint(pr1.x);
                uint32_t brl0 = __float_as_uint(pr0.y);
                uint32_t brl1 = __float_as_uint(pr1.y);
                mma_tf32(accR[j], ah0, ah1, ah2, ah3, brh0, brh1);
                mma_tf32(accR[j], ah0, ah1, ah2, ah3, brl0, brl1);
                mma_tf32(accR[j], al0, al1, al2, al3, brh0, brh1);
            }
        }
    }

    // store: c0/c1 -> (r0, col, col+1); c2/c3 -> (r1, col, col+1)
    int colb = 2 * kq;
#pragma unroll
    for (int j = 0; j < 8; j++) {
        int c = j * 8 + colb;
        float bx = bias[c], by = bias[c + 1];
        if (v0) {
            *(float2*)(g_yl + (size_t)r0 * 64 + c) = make_float2(accL[j][0], accL[j][1]);
            *(float2*)(g_yr + (size_t)r0 * 64 + c) = make_float2(accR[j][0] + bx, accR[j][1] + by);
        }
        if (v1) {
            *(float2*)(g_yl + (size_t)r1 * 64 + c) = make_float2(accL[j][2], accL[j][3]);
            *(float2*)(g_yr + (size_t)r1 * 64 + c) = make_float2(accR[j][2] + bx, accR[j][3] + by);
        }
    }
}

// ---------------- aggregation: out[n] = mean_{e in CSR(n)} yl[src_e] + yr[n] ----
__global__ __launch_bounds__(256)
void aggregate_kernel(int out_id) {
    float* out = buf_by_id(out_id);
    int tid = blockIdx.x * blockDim.x + threadIdx.x;
    int node = tid >> 4;             // 16 threads per node
    int lane = threadIdx.x & 15;     // covers 64 floats as float4
    if (node >= N_NODES) return;
    int start = g_off[node];
    int d = g_deg[node];

    float4 a = make_float4(0.f, 0.f, 0.f, 0.f);
    const int* csr = g_csr + start;
    int e = 0;
    for (; e + 4 <= d; e += 4) {
        int s0 = csr[e + 0];
        int s1 = csr[e + 1];
        int s2 = csr[e + 2];
        int s3 = csr[e + 3];
        float4 v0 = *(const float4*)(g_yl + (size_t)s0 * 64 + lane * 4);
        float4 v1 = *(const float4*)(g_yl + (size_t)s1 * 64 + lane * 4);
        float4 v2 = *(const float4*)(g_yl + (size_t)s2 * 64 + lane * 4);
        float4 v3 = *(const float4*)(g_yl + (size_t)s3 * 64 + lane * 4);
        a.x += v0.x + v1.x + v2.x + v3.x;
        a.y += v0.y + v1.y + v2.y + v3.y;
        a.z += v0.z + v1.z + v2.z + v3.z;
        a.w += v0.w + v1.w + v2.w + v3.w;
    }
    for (; e < d; e++) {
        int s = csr[e];
        float4 v = *(const float4*)(g_yl + (size_t)s * 64 + lane * 4);
        a.x += v.x; a.y += v.y; a.z += v.z; a.w += v.w;
    }
    float inv = (d > 0) ? (1.0f / (float)d) : 0.0f;
    float4 r = *(const float4*)(g_yr + (size_t)node * 64 + lane * 4);
    float4 o;
    o.x = a.x * inv + r.x;
    o.y = a.y * inv + r.y;
    o.z = a.z * inv + r.z;
    o.w = a.w * inv + r.w;
    *(float4*)(out + (size_t)node * 64 + lane * 4) = o;
}

// ---------------- global mean pool (batch sorted) ----------------
__global__ void pool_kernel(int in_id) {
    const float* h = buf_by_id(in_id);
    int f = threadIdx.x & 63;
    int sub = threadIdx.x >> 6;
    int base = blockIdx.x * 128 + sub * 32;
    if (base >= N_NODES) return;
    int end = base + 32;
    if (end > N_NODES) end = N_NODES;
    float run = 0.0f, cnt = 0.0f;
    int cur = -1;
    for (int n = base; n < end; n++) {
        int b = g_batch[n];
        if (b != cur) {
            if (cur >= 0) {
                atomicAdd(&g_pool[cur * 64 + f], run);
                if (f == 0) atomicAdd(&g_pcnt[cur], cnt);
            }
            run = 0.0f; cnt = 0.0f; cur = b;
        }
        run += h[(size_t)n * 64 + f];
        cnt += 1.0f;
    }
    if (cur >= 0) {
        atomicAdd(&g_pool[cur * 64 + f], run);
        if (f == 0) atomicAdd(&g_pcnt[cur], cnt);
    }
}

// ---------------- MLP head ----------------
__global__ void mlp_gemm(int stage, const float* __restrict__ W,
                         const float* __restrict__ b, float* __restrict__ ext_out,
                         int K, int Nout) {
    const float* in;
    float* out;
    switch (stage) {
        case 0: in = g_pool; out = g_m1; break;
        case 1: in = g_m1;   out = g_m2; break;
        case 2: in = g_m2;   out = g_m3; break;
        default: in = g_m3;  out = ext_out; break;
    }
    int idx = blockIdx.x * blockDim.x + threadIdx.x;
    if (idx >= NUM_GRAPHS * Nout) return;
    int r = idx / Nout;
    int j = idx - r * Nout;
    float acc = 0.0f;
    const float* ir = in + (size_t)r * K;
    for (int k = 0; k < K; k++) acc += ir[k] * W[(size_t)k * Nout + j];
    if (stage == 0) acc *= 1.0f / fmaxf(g_pcnt[r], 1.0f);
    out[idx] = acc + b[j];
}

// one block per column; blockDim = NUM_GRAPHS = 256
__global__ void bn_tanh_kernel(int which, const float* __restrict__ g,
                               const float* __restrict__ be, int ncols) {
    float* y = (which == 0) ? g_m1 : (which == 1) ? g_m2 : g_m3;
    __shared__ float sd[256];
    __shared__ float sm[2];
    int j = blockIdx.x;
    int t = threadIdx.x;
    float v = y[(size_t)t * ncols + j];
    sd[t] = v;
    __syncthreads();
    for (int s = 128; s > 0; s >>= 1) {
        if (t < s) sd[t] += sd[t + s];
        __syncthreads();
    }
    if (t == 0) sm[0] = sd[0] * (1.0f / NUM_GRAPHS);
    __syncthreads();
    float mean = sm[0];
    float d = v - mean;
    sd[t] = d * d;
    __syncthreads();
    for (int s = 128; s > 0; s >>= 1) {
        if (t < s) sd[t] += sd[t + s];
        __syncthreads();
    }
    if (t == 0) sm[1] = sd[0] * (1.0f / NUM_GRAPHS);
    __syncthreads();
    float var = sm[1];
    float o = d * rsqrtf(var + EPS) * g[j] + be[j];
    y[(size_t)t * ncols + j] = tanhf(o);
}

// ---------------- launch ----------------
extern "C" void kernel_launch(void* const* d_in, const int* in_sizes, int n_in,
                              void* d_out, int out_size) {
    const float* x     = (const float*)d_in[0];
    const void*  eidx  = d_in[1];
    const void*  batch = d_in[2];
    const float* W1l = (const float*)d_in[3];
    const float* b1l = (const float*)d_in[4];
    const float* W1r = (const float*)d_in[5];
    const float* W2l = (const float*)d_in[6];
    const float* b2l = (const float*)d_in[7];
    const float* W2r = (const float*)d_in[8];
    const float* W3l = (const float*)d_in[9];
    const float* b3l = (const float*)d_in[10];
    const float* W3r = (const float*)d_in[11];
    const float* lin1_w = (const float*)d_in[12];
    const float* lin1_b = (const float*)d_in[13];
    const float* g1  = (const float*)d_in[14];
    const float* be1 = (const float*)d_in[15];
    const float* lin2_w = (const float*)d_in[16];
    const float* lin2_b = (const float*)d_in[17];
    const float* g2  = (const float*)d_in[18];
    const float* be2 = (const float*)d_in[19];
    const float* lin3_w = (const float*)d_in[20];
    const float* lin3_b = (const float*)d_in[21];
    const float* g3  = (const float*)d_in[22];
    const float* be3 = (const float*)d_in[23];
    const float* lin4_w = (const float*)d_in[24];
    const float* lin4_b = (const float*)d_in[25];
    float* out = (float*)d_out;

    const int EB = (N_EDGES + 255) / 256;        // 3125
    const int NBn = (N_NODES + 255) / 256;       // 196
    const int GB = (N_NODES + 127) / 128;        // 391 (128 rows per block)
    const int AB = (N_NODES * 16 + 255) / 256;   // 3125 (16 threads/node)

    // zero BEFORE convert (fused degree histogram)
    zero_kernel<<<NBn, 256>>>();
    convert_edges<<<EB, 256>>>(eidx);
    convert_batch<<<NBn, 256>>>(batch, eidx);

    // CSR build (blocksum + fused scan)
    blocksum_kernel<<<SCAN_NB, SCAN_B>>>();
    block_scan_kernel<<<SCAN_NB, SCAN_B>>>();
    fill_kernel<<<EB, 256>>>();

    // Layer 1: linear-first (tensor core, 3-pass tf32), then aggregate
    gemm_dual_tc3<<<GB, 256>>>(x, -1, W1l, b1l, W1r, IN_DIM);
    aggregate_kernel<<<AB, 256>>>(2);
    // Layer 2
    gemm_dual_tc3<<<GB, 256>>>(nullptr, 2, W2l, b2l, W2r, H_DIM);
    aggregate_kernel<<<AB, 256>>>(3);
    // Layer 3
    gemm_dual_tc3<<<GB, 256>>>(nullptr, 3, W3l, b3l, W3r, H_DIM);
    aggregate_kernel<<<AB, 256>>>(2);

    // global mean pool (division folded into mlp stage 0)
    pool_kernel<<<GB, 256>>>(2);

    // MLP head (fp32-exact)
    mlp_gemm<<<(NUM_GRAPHS * HID + 255) / 256, 256>>>(0, lin1_w, lin1_b, nullptr,
                                                      H_DIM, HID);
    bn_tanh_kernel<<<HID, 256>>>(0, g1, be1, HID);
    mlp_gemm<<<(NUM_GRAPHS * (HID / 2) + 255) / 256, 256>>>(1, lin2_w, lin2_b, nullptr,
                                                            HID, HID / 2);
    bn_tanh_kernel<<<HID / 2, 256>>>(1, g2, be2, HID / 2);
    mlp_gemm<<<(NUM_GRAPHS * (HID / 4) + 255) / 256, 256>>>(2, lin3_w, lin3_b, nullptr,
                                                            HID / 2, HID / 4);
    bn_tanh_kernel<<<HID / 4, 256>>>(2, g3, be3, HID / 4);
    mlp_gemm<<<(NUM_GRAPHS * 10 + 255) / 256, 256>>>(3, lin4_w, lin4_b, out,
                                                     HID / 4, 10);
}